// round 4
// baseline (speedup 1.0000x reference)
#include <cuda_runtime.h>

// PoseCost: SE(3) log-map pose error, N = B*H poses.
// Outputs: [0,N) cost | [N,2N) rot_err | [2N,3N) pos_err | [3N,6N) v | [6N,9N) omega
//
// Smem-staged kernel: 1 pose/thread (low regs -> high occupancy) + block-level
// float4 staging of rot/pos/v/omega through shared memory (clean 128B
// transactions). cost/rot_err/pos_err stores are naturally coalesced scalars.

#define EPS 1e-7f
#define SMALL 1e-4f
#define ROT_ERR_W 15.0f
#define TRANS_ERR_W 100.0f
#define TPB 256

__device__ __forceinline__ void pose_compute(
    const float* __restrict__ R,   // 9 floats row-major
    float d0, float d1, float d2,  // goal_pos - pos
    const float* __restrict__ G,   // goal rot 9
    float w0, float w1, float w2, float w3, float w4, float w5,
    float& cost, float& rot_err, float& pos_err,
    float& v0, float& v1, float& v2,
    float& o0, float& o1, float& o2)
{
    float t0 = R[0]*d0 + R[3]*d1 + R[6]*d2;
    float t1 = R[1]*d0 + R[4]*d1 + R[7]*d2;
    float t2 = R[2]*d0 + R[5]*d1 + R[8]*d2;

    float Rge00 = R[0]*G[0] + R[3]*G[3] + R[6]*G[6];
    float Rge11 = R[1]*G[1] + R[4]*G[4] + R[7]*G[7];
    float Rge22 = R[2]*G[2] + R[5]*G[5] + R[8]*G[8];
    float Rge21 = R[2]*G[1] + R[5]*G[4] + R[8]*G[7];
    float Rge12 = R[1]*G[2] + R[4]*G[5] + R[7]*G[8];
    float Rge02 = R[0]*G[2] + R[3]*G[5] + R[6]*G[8];
    float Rge20 = R[2]*G[0] + R[5]*G[3] + R[8]*G[6];
    float Rge10 = R[1]*G[0] + R[4]*G[3] + R[7]*G[6];
    float Rge01 = R[0]*G[1] + R[3]*G[4] + R[6]*G[7];

    float tr = Rge00 + Rge11 + Rge22;
    float cos_t = (tr - 1.0f) * 0.5f;
    cos_t = fminf(fmaxf(cos_t, -1.0f + EPS), 1.0f - EPS);
    float theta = acosf(cos_t);
    float sin_t = sinf(theta);   // exact reference numerics (1/sin amplification)

    float wv0 = 0.5f * (Rge21 - Rge12);
    float wv1 = 0.5f * (Rge02 - Rge20);
    float wv2 = 0.5f * (Rge10 - Rge01);

    bool small = theta < SMALL;
    float scale = small ? (1.0f + theta * theta * (1.0f / 6.0f))
                        : (theta / sin_t);
    o0 = scale * wv0;
    o1 = scale * wv1;
    o2 = scale * wv2;

    float theta2 = small ? 1.0f : theta * theta;
    float A = small ? (1.0f / 12.0f)
                    : (1.0f - (theta * sin_t) / (2.0f * (1.0f - cos_t))) / theta2;

    float n2 = o0*o0 + o1*o1 + o2*o2;
    float ot = o0*t0 + o1*t1 + o2*t2;
    float cx0 = o1*t2 - o2*t1;
    float cx1 = o2*t0 - o0*t2;
    float cx2 = o0*t1 - o1*t0;
    v0 = t0 - 0.5f*cx0 + A*(o0*ot - n2*t0);
    v1 = t1 - 0.5f*cx1 + A*(o1*ot - n2*t1);
    v2 = t2 - 0.5f*cx2 + A*(o2*ot - n2*t2);

    float pw0 = w3*v0, pw1 = w4*v1, pw2 = w5*v2;
    float rw0 = w0*o0, rw1 = w1*o1, rw2 = w2*o2;
    pos_err = pw0*pw0 + pw1*pw1 + pw2*pw2;
    rot_err = rw0*rw0 + rw1*rw1 + rw2*rw2;
    cost = ROT_ERR_W * rot_err + TRANS_ERR_W * pos_err;
}

__global__ __launch_bounds__(TPB) void pose_cost_kernel_smem(
    const float* __restrict__ pos,
    const float* __restrict__ rot,
    const float* __restrict__ goal_pos,
    const float* __restrict__ goal_rot,
    const float* __restrict__ vw,
    float* __restrict__ out,
    int N,
    int vec_ok)   // 1 if N % 4 == 0 (float4 views of output regions aligned)
{
    __shared__ float sR[TPB * 9];   // rot staging; reused for v staging
    __shared__ float sP[TPB * 3];   // pos staging; reused for omega staging

    int tid = threadIdx.x;
    int base = blockIdx.x * TPB;
    if (base >= N) return;
    bool full = vec_ok && (base + TPB <= N);

    float G[9];
#pragma unroll
    for (int i = 0; i < 9; i++) G[i] = __ldg(&goal_rot[i]);
    float gp0 = __ldg(&goal_pos[0]);
    float gp1 = __ldg(&goal_pos[1]);
    float gp2 = __ldg(&goal_pos[2]);
    float w0 = __ldg(&vw[0]), w1 = __ldg(&vw[1]), w2 = __ldg(&vw[2]);
    float w3 = __ldg(&vw[3]), w4 = __ldg(&vw[4]), w5 = __ldg(&vw[5]);

    float R[9], p0, p1, p2;

    if (full) {
        // ---- coalesced float4 staging loads ----
        const float4* rv = (const float4*)(rot + (size_t)base * 9); // 576 float4
        float4* sRv = (float4*)sR;
#pragma unroll
        for (int i = tid; i < TPB * 9 / 4; i += TPB) sRv[i] = rv[i];
        const float4* pv = (const float4*)(pos + (size_t)base * 3); // 192 float4
        float4* sPv = (float4*)sP;
        if (tid < TPB * 3 / 4) sPv[tid] = pv[tid];
        __syncthreads();
#pragma unroll
        for (int k = 0; k < 9; k++) R[k] = sR[tid * 9 + k];   // gcd(9,32)=1: no conflicts
        p0 = sP[tid * 3 + 0];                                  // gcd(3,32)=1: no conflicts
        p1 = sP[tid * 3 + 1];
        p2 = sP[tid * 3 + 2];
    } else {
        int idx = base + tid;
        if (idx >= N) return;
        const float* Rp = rot + (size_t)idx * 9;
#pragma unroll
        for (int k = 0; k < 9; k++) R[k] = Rp[k];
        const float* Pp = pos + (size_t)idx * 3;
        p0 = Pp[0]; p1 = Pp[1]; p2 = Pp[2];
    }

    float cost, rot_err, pos_err, v0, v1, v2, o0, o1, o2;
    pose_compute(R, gp0 - p0, gp1 - p1, gp2 - p2,
                 G, w0, w1, w2, w3, w4, w5,
                 cost, rot_err, pos_err, v0, v1, v2, o0, o1, o2);

    int idx = base + tid;
    // scalar stores: contiguous across lanes -> fully coalesced
    out[idx] = cost;
    out[(size_t)N + idx] = rot_err;
    out[2ull * N + idx] = pos_err;

    if (full) {
        __syncthreads();  // everyone done reading sR/sP before overwrite
        sR[tid * 3 + 0] = v0;  sR[tid * 3 + 1] = v1;  sR[tid * 3 + 2] = v2;
        sP[tid * 3 + 0] = o0;  sP[tid * 3 + 1] = o1;  sP[tid * 3 + 2] = o2;
        __syncthreads();
        // coalesced float4 staging stores
        float4* ov = (float4*)(out + 3ull * N + (size_t)base * 3); // 192 float4
        float4* oo = (float4*)(out + 6ull * N + (size_t)base * 3);
        const float4* sRv = (const float4*)sR;
        const float4* sPv = (const float4*)sP;
        if (tid < TPB * 3 / 4) {
            ov[tid] = sRv[tid];
            oo[tid] = sPv[tid];
        }
    } else {
        float* ov = out + 3ull * N + (size_t)idx * 3;
        ov[0] = v0; ov[1] = v1; ov[2] = v2;
        float* oo = out + 6ull * N + (size_t)idx * 3;
        oo[0] = o0; oo[1] = o1; oo[2] = o2;
    }
}

extern "C" void kernel_launch(void* const* d_in, const int* in_sizes, int n_in,
                              void* d_out, int out_size)
{
    const float* pos      = (const float*)d_in[0];
    const float* rot      = (const float*)d_in[1];
    const float* goal_pos = (const float*)d_in[2];
    const float* goal_rot = (const float*)d_in[3];
    const float* vw       = (const float*)d_in[4];

    int N = in_sizes[0] / 3;
    int vec_ok = ((N & 3) == 0) ? 1 : 0;

    int blocks = (N + TPB - 1) / TPB;
    pose_cost_kernel_smem<<<blocks, TPB>>>(pos, rot, goal_pos, goal_rot, vw,
                                           (float*)d_out, N, vec_ok);
}